// round 12
// baseline (speedup 1.0000x reference)
#include <cuda_runtime.h>
#include <cstdint>

#define BATCH   2
#define HEADS   16
#define SEQ     2048
#define DKV     64
#define DMODEL  1024
#define MTOT    (BATCH * SEQ)      // 4096 rows
#define BIAS_PAD    4352
#define BIAS_CENTER 2176
#define QKV_ELEMS (BATCH * HEADS * SEQ * DKV)

// ---------------- bf16 pack + tensor-core helpers ---------------------------
// returns packed b16x2: low half = bf16(lo_e), high half = bf16(hi_e)
__device__ __forceinline__ uint32_t bfpack(float lo_e, float hi_e) {
    uint32_t r; asm("cvt.rn.bf16x2.f32 %0, %1, %2;" : "=r"(r) : "f"(hi_e), "f"(lo_e));
    return r;
}
__device__ __forceinline__ uint32_t smem_u32(const void* p) {
    uint32_t a;
    asm("{ .reg .u64 t; cvta.to.shared.u64 t, %1; cvt.u32.u64 %0, t; }" : "=r"(a) : "l"(p));
    return a;
}
__device__ __forceinline__ void ldm_x4(uint32_t* r, uint32_t addr) {
    asm volatile("ldmatrix.sync.aligned.m8n8.x4.shared.b16 {%0,%1,%2,%3}, [%4];"
        : "=r"(r[0]), "=r"(r[1]), "=r"(r[2]), "=r"(r[3]) : "r"(addr));
}
__device__ __forceinline__ void ldm_x4t(uint32_t* r, uint32_t addr) {
    asm volatile("ldmatrix.sync.aligned.m8n8.x4.trans.shared.b16 {%0,%1,%2,%3}, [%4];"
        : "=r"(r[0]), "=r"(r[1]), "=r"(r[2]), "=r"(r[3]) : "r"(addr));
}
__device__ __forceinline__ void mma_b(float* c, const uint32_t* a, uint32_t b0, uint32_t b1) {
    asm volatile("mma.sync.aligned.m16n8k16.row.col.f32.bf16.bf16.f32 "
        "{%0,%1,%2,%3}, {%4,%5,%6,%7}, {%8,%9}, {%0,%1,%2,%3};"
        : "+f"(c[0]), "+f"(c[1]), "+f"(c[2]), "+f"(c[3])
        : "r"(a[0]), "r"(a[1]), "r"(a[2]), "r"(a[3]), "r"(b0), "r"(b1));
}
// cp.async: 16-byte gmem -> smem, bypassing registers
__device__ __forceinline__ void cp16(uint32_t dst, const void* src) {
    asm volatile("cp.async.cg.shared.global [%0], [%1], 16;" :: "r"(dst), "l"(src));
}
#define CP_COMMIT()  asm volatile("cp.async.commit_group;" ::: "memory")
#define CP_WAIT(n)   asm volatile("cp.async.wait_group %0;" :: "n"(n) : "memory")

// split a float4 into packed-bf16 hi pair + residual-lo pair
__device__ __forceinline__ void split4(float4 v, uint2& hi, uint2& lo) {
    uint32_t h01 = bfpack(v.x, v.y), h23 = bfpack(v.z, v.w);
    float l0 = v.x - __uint_as_float(h01 << 16);
    float l1 = v.y - __uint_as_float(h01 & 0xffff0000u);
    float l2 = v.z - __uint_as_float(h23 << 16);
    float l3 = v.w - __uint_as_float(h23 & 0xffff0000u);
    hi = make_uint2(h01, h23);
    lo = make_uint2(bfpack(l0, l1), bfpack(l2, l3));
}

// ---------------- scratch (device globals: allocation-guard safe) -----------
__device__ __align__(16) uint16_t g_ahi[MTOT * DMODEL],  g_alo[MTOT * DMODEL];
__device__ __align__(16) uint16_t g_whi[4 * DMODEL * DMODEL], g_wlo[4 * DMODEL * DMODEL];
__device__ __align__(16) uint16_t g_qhi[QKV_ELEMS], g_qlo[QKV_ELEMS];
__device__ __align__(16) uint16_t g_khi[QKV_ELEMS], g_klo[QKV_ELEMS];
__device__ __align__(16) uint16_t g_vhi[QKV_ELEMS], g_vlo[QKV_ELEMS];
__device__ __align__(16) uint16_t g_phi[MTOT * DMODEL], g_plo[MTOT * DMODEL];
__device__ float g_bias[HEADS * BIAS_PAD];

// ---------------- T5 relative-position bias ---------------------------------
__global__ void bias_kernel(const float* __restrict__ table) {
    int i = blockIdx.x * blockDim.x + threadIdx.x;
    if (i >= HEADS * BIAS_PAD) return;
    int h = i / BIAS_PAD;
    int delta = (i % BIAS_PAD) - BIAS_CENTER;
    float v = 0.0f;
    int rp = delta < 0 ? -delta : delta;
    if (rp <= SEQ - 1) {
        int base = (delta > 0) ? 16 : 0;
        int bucket;
        if (rp < 8) {
            bucket = base + rp;
        } else {
            float ratio = logf((float)rp * 0.125f) / (float)2.772588722239781;
            int rpl = 8 + (int)(ratio * 8.0f);
            bucket = base + (rpl < 15 ? rpl : 15);
        }
        v = table[bucket * HEADS + h];
    }
    g_bias[i] = v;
}

// ---------------- one-time split passes --------------------------------------
__global__ void split_hidden(const float* __restrict__ x) {
    int i = blockIdx.x * blockDim.x + threadIdx.x;
    if (i >= MTOT * DMODEL / 4) return;
    uint2 hi, lo;
    split4(((const float4*)x)[i], hi, lo);
    ((uint2*)g_ahi)[i] = hi;
    ((uint2*)g_alo)[i] = lo;
}
__global__ void split_w(const float* __restrict__ Wq, const float* __restrict__ Wk,
                        const float* __restrict__ Wv, const float* __restrict__ Wo) {
    int z = blockIdx.z;
    const float* W = (z == 0) ? Wq : (z == 1) ? Wk : (z == 2) ? Wv : Wo;
    int i = blockIdx.x * blockDim.x + threadIdx.x;
    if (i >= DMODEL * DMODEL / 4) return;
    uint2 hi, lo;
    split4(((const float4*)W)[i], hi, lo);
    size_t o = (size_t)z * (DMODEL * DMODEL / 4) + i;
    ((uint2*)g_whi)[o] = hi;
    ((uint2*)g_wlo)[o] = lo;
}

// ---------------- bf16-split tensor-core GEMM, cp.async 2-stage (round 11) --
#define APITCH 80
#define BPITCH 272
#define ST_ALO 10240
#define ST_BHI 20480
#define ST_BLO 29184
#define STAGE_BYTES 37888
#define GEMM_SMEM (2 * STAGE_BYTES)

__global__ __launch_bounds__(256) void gemm_bf16(int a_sel, int qkv_mode, int wbase,
                                                 float* __restrict__ outp) {
    extern __shared__ __align__(16) char sm[];

    const uint16_t* Ah = a_sel ? g_phi : g_ahi;
    const uint16_t* Al = a_sel ? g_plo : g_alo;

    int tid = threadIdx.x, lane = tid & 31, wid = tid >> 5;
    int wm = wid >> 2, wn = wid & 3;
    int n0 = blockIdx.x * 128, m0 = blockIdx.y * 128;
    int z = blockIdx.z;
    const uint16_t* Wh = g_whi + (size_t)(wbase + z) * DMODEL * DMODEL;
    const uint16_t* Wl = g_wlo + (size_t)(wbase + z) * DMODEL * DMODEL;

    uint32_t sb = smem_u32(sm);

    int a_row[2], a_seg[2], b_row[2], b_seg[2];
#pragma unroll
    for (int r = 0; r < 2; r++) {
        int idx = tid + r * 256;
        a_row[r] = idx >> 2;  a_seg[r] = idx & 3;
        b_row[r] = idx >> 4;  b_seg[r] = idx & 15;
    }

    float acc[4][4][4];
#pragma unroll
    for (int a = 0; a < 4; a++)
#pragma unroll
        for (int b = 0; b < 4; b++)
#pragma unroll
            for (int c = 0; c < 4; c++) acc[a][b][c] = 0.0f;

    uint32_t aoff = (uint32_t)((wm * 64 + (lane & 15)) * APITCH + (lane >> 4) * 16);
    uint32_t boff = (uint32_t)(((lane & 7) + ((lane >> 3) & 1) * 8) * BPITCH
                               + (wn * 32 + (lane >> 4) * 8) * 2);

    auto issue = [&](int ch, int buf) {
        int k0 = ch * 32;
        uint32_t st = sb + buf * STAGE_BYTES;
#pragma unroll
        for (int r = 0; r < 2; r++) {
            uint32_t d = st + a_row[r] * APITCH + a_seg[r] * 16;
            size_t go = (size_t)(m0 + a_row[r]) * DMODEL + k0 + a_seg[r] * 8;
            cp16(d, Ah + go);
            cp16(d + ST_ALO, Al + go);
            uint32_t db = st + ST_BHI + b_row[r] * BPITCH + b_seg[r] * 16;
            size_t gb = (size_t)(k0 + b_row[r]) * DMODEL + n0 + b_seg[r] * 8;
            cp16(db, Wh + gb);
            cp16(db + (ST_BLO - ST_BHI), Wl + gb);
        }
        CP_COMMIT();
    };

    issue(0, 0);
    for (int ch = 0; ch < 32; ch++) {
        int buf = ch & 1;
        if (ch < 31) issue(ch + 1, buf ^ 1);
        if (ch < 31) { CP_WAIT(1); } else { CP_WAIT(0); }
        __syncthreads();

        uint32_t st = sb + buf * STAGE_BYTES;
#pragma unroll
        for (int ks = 0; ks < 2; ks++) {
            uint32_t ahf[4][4], alf[4][4], bhf[2][4], blf[2][4];
#pragma unroll
            for (int mf = 0; mf < 4; mf++) {
                uint32_t ad = st + aoff + mf * (16 * APITCH) + ks * 32;
                ldm_x4(ahf[mf], ad);
                ldm_x4(alf[mf], ad + ST_ALO);
            }
#pragma unroll
            for (int nf2 = 0; nf2 < 2; nf2++) {
                uint32_t bd = st + ST_BHI + boff + nf2 * 32 + ks * (16 * BPITCH);
                ldm_x4t(bhf[nf2], bd);
                ldm_x4t(blf[nf2], bd + (ST_BLO - ST_BHI));
            }
#pragma unroll
            for (int mf = 0; mf < 4; mf++)
#pragma unroll
                for (int nf = 0; nf < 4; nf++) {
                    uint32_t b0 = bhf[nf >> 1][(nf & 1) * 2];
                    uint32_t b1 = bhf[nf >> 1][(nf & 1) * 2 + 1];
                    uint32_t c0 = blf[nf >> 1][(nf & 1) * 2];
                    uint32_t c1 = blf[nf >> 1][(nf & 1) * 2 + 1];
                    mma_b(acc[mf][nf], ahf[mf], b0, b1);
                    mma_b(acc[mf][nf], ahf[mf], c0, c1);
                    mma_b(acc[mf][nf], alf[mf], b0, b1);
                }
        }
        __syncthreads();
    }

    // ---- epilogue ----
    int g = lane >> 2, tg = lane & 3;
    uint16_t* dh = (z == 0) ? g_qhi : (z == 1) ? g_khi : g_vhi;
    uint16_t* dl = (z == 0) ? g_qlo : (z == 1) ? g_klo : g_vlo;
#pragma unroll
    for (int mf = 0; mf < 4; mf++) {
        int r0 = m0 + wm * 64 + mf * 16 + g;
#pragma unroll
        for (int nf = 0; nf < 4; nf++) {
            int c = n0 + wn * 32 + nf * 8 + tg * 2;
            if (qkv_mode) {
                int h = c >> 6, d = c & 63;
#pragma unroll
                for (int half = 0; half < 2; half++) {
                    int r = r0 + half * 8;
                    int b = r >> 11, s = r & (SEQ - 1);
                    float v0 = acc[mf][nf][half * 2], v1 = acc[mf][nf][half * 2 + 1];
                    uint32_t uh = bfpack(v0, v1);
                    float e0 = v0 - __uint_as_float(uh << 16);
                    float e1 = v1 - __uint_as_float(uh & 0xffff0000u);
                    uint32_t ul = bfpack(e0, e1);
                    size_t idx = ((((size_t)(b * HEADS + h)) * SEQ + s) << 6) + d;
                    *(uint32_t*)&dh[idx] = uh;
                    *(uint32_t*)&dl[idx] = ul;
                }
            } else {
                *(float2*)&outp[(size_t)r0 * DMODEL + c] =
                    make_float2(acc[mf][nf][0], acc[mf][nf][1]);
                *(float2*)&outp[(size_t)(r0 + 8) * DMODEL + c] =
                    make_float2(acc[mf][nf][2], acc[mf][nf][3]);
            }
        }
    }
}

// ---------------- tensor-core flash attention, cp.async 2-stage K/V ring ----
#define KTILE 64
#define PITCH 144
#define PL 9216                 // one 64-row plane (64 * 144)
#define KV_STAGE (4 * PL)       // Khi | Klo | Vhi | Vlo = 36864 B
#define AT_QLO 18432            // Q lo plane offset (Q staged in stage 0)
#define ATT_SMEM (2 * KV_STAGE) // 73728 B dynamic

__global__ __launch_bounds__(256) void attn_tc() {
    extern __shared__ __align__(16) char smA[];
    __shared__ float bias_s[192];

    int tid = threadIdx.x, lane = tid & 31, w = tid >> 5;
    int h = blockIdx.y, b = blockIdx.z;
    int bh = b * HEADS + h;
    int q0 = blockIdx.x * 128;

    uint32_t sb = smem_u32(smA);

    // ---- stage Q tile (pre-split planes, pure copy; occupies stage 0) ----
    {
        int qrow = tid >> 1, qc0 = (tid & 1) * 32;
        const uint16_t* qpH = g_qhi + ((size_t)bh * SEQ + q0 + qrow) * 64 + qc0;
        const uint16_t* qpL = g_qlo + ((size_t)bh * SEQ + q0 + qrow) * 64 + qc0;
        char* p = smA + qrow * PITCH + qc0 * 2;
#pragma unroll
        for (int i = 0; i < 4; i++) {
            *(uint4*)(p + i * 16) = *(const uint4*)(qpH + i * 8);
            *(uint4*)(p + AT_QLO + i * 16) = *(const uint4*)(qpL + i * 8);
        }
    }
    __syncthreads();

    // ---- Q fragments to registers ----
    uint32_t qh[4][4], ql[4][4];
#pragma unroll
    for (int ks = 0; ks < 4; ks++) {
        uint32_t ad = sb + (w * 16 + (lane & 15)) * PITCH + (lane >> 4) * 16 + ks * 32;
        ldm_x4(qh[ks], ad);
        ldm_x4(ql[ks], ad + AT_QLO);
    }
    __syncthreads();   // all warps done reading Q smem before K/V ring overwrites

    // ---- cp.async K/V tile issue: 4 planes x 2 ops/thread ----
    auto issue = [&](int kt, int buf) {
        int kbase = kt * KTILE;
        uint32_t st = sb + buf * KV_STAGE;
#pragma unroll
        for (int r = 0; r < 2; r++) {
            int idx = tid + r * 256;
            int row = idx >> 3, seg = idx & 7;
            size_t go = ((size_t)bh * SEQ + kbase + row) * 64 + seg * 8;
            uint32_t d = st + row * PITCH + seg * 16;
            cp16(d,          g_khi + go);
            cp16(d + PL,     g_klo + go);
            cp16(d + 2 * PL, g_vhi + go);
            cp16(d + 3 * PL, g_vlo + go);
        }
        CP_COMMIT();
    };

    float Oacc[8][4];
#pragma unroll
    for (int nf = 0; nf < 8; nf++)
#pragma unroll
        for (int j = 0; j < 4; j++) Oacc[nf][j] = 0.0f;

    float m_lo = -1e30f, m_hi = -1e30f, l_lo = 0.0f, l_hi = 0.0f;
    int rq = lane >> 2, cq = 2 * (lane & 3);
    int rt = w * 16 + rq;

    issue(0, 0);
    for (int kt = 0; kt < SEQ / KTILE; kt++) {
        int buf = kt & 1;
        int kbase = kt * KTILE;
        if (kt < SEQ / KTILE - 1) issue(kt + 1, buf ^ 1);
        if (tid < 192)
            bias_s[tid] = g_bias[h * BIAS_PAD + BIAS_CENTER + kbase - q0 + tid - 127];
        if (kt < SEQ / KTILE - 1) { CP_WAIT(1); } else { CP_WAIT(0); }
        __syncthreads();

        uint32_t st = sb + buf * KV_STAGE;

        // ---- S = Q . K^T (3-split) ----
        float Sv[8][4];
#pragma unroll
        for (int nf = 0; nf < 8; nf++)
#pragma unroll
            for (int j = 0; j < 4; j++) Sv[nf][j] = 0.0f;

#pragma unroll
        for (int nf2 = 0; nf2 < 4; nf2++) {
#pragma unroll
            for (int ks = 0; ks < 4; ks++) {
                uint32_t kh4[4], kl4[4];
                uint32_t ad = st + (nf2 * 16 + (lane & 7) + ((lane >> 4) << 3)) * PITCH
                              + ((lane >> 3) & 1) * 16 + ks * 32;
                ldm_x4(kh4, ad);
                ldm_x4(kl4, ad + PL);
                mma_b(Sv[2 * nf2],     qh[ks], kh4[0], kh4[1]);
                mma_b(Sv[2 * nf2],     qh[ks], kl4[0], kl4[1]);
                mma_b(Sv[2 * nf2],     ql[ks], kh4[0], kh4[1]);
                mma_b(Sv[2 * nf2 + 1], qh[ks], kh4[2], kh4[3]);
                mma_b(Sv[2 * nf2 + 1], qh[ks], kl4[2], kl4[3]);
                mma_b(Sv[2 * nf2 + 1], ql[ks], kh4[2], kh4[3]);
            }
        }

        // ---- bias + online softmax ----
        const float* bw = bias_s + 127 - rt;
        float mt_lo = -1e30f, mt_hi = -1e30f;
#pragma unroll
        for (int nf = 0; nf < 8; nf++) {
            int c = nf * 8 + cq;
            Sv[nf][0] += bw[c];
            Sv[nf][1] += bw[c + 1];
            Sv[nf][2] += bw[c - 8];
            Sv[nf][3] += bw[c - 7];
            mt_lo = fmaxf(mt_lo, fmaxf(Sv[nf][0], Sv[nf][1]));
            mt_hi = fmaxf(mt_hi, fmaxf(Sv[nf][2], Sv[nf][3]));
        }
        mt_lo = fmaxf(mt_lo, __shfl_xor_sync(0xffffffffu, mt_lo, 1));
        mt_lo = fmaxf(mt_lo, __shfl_xor_sync(0xffffffffu, mt_lo, 2));
        mt_hi = fmaxf(mt_hi, __shfl_xor_sync(0xffffffffu, mt_hi, 1));
        mt_hi = fmaxf(mt_hi, __shfl_xor_sync(0xffffffffu, mt_hi, 2));

        float mn_lo = fmaxf(m_lo, mt_lo), mn_hi = fmaxf(m_hi, mt_hi);
        float corr_lo = __expf(m_lo - mn_lo), corr_hi = __expf(m_hi - mn_hi);
        m_lo = mn_lo; m_hi = mn_hi;

        float ps_lo = 0.0f, ps_hi = 0.0f;
#pragma unroll
        for (int nf = 0; nf < 8; nf++) {
            Sv[nf][0] = __expf(Sv[nf][0] - mn_lo);
            Sv[nf][1] = __expf(Sv[nf][1] - mn_lo);
            Sv[nf][2] = __expf(Sv[nf][2] - mn_hi);
            Sv[nf][3] = __expf(Sv[nf][3] - mn_hi);
            ps_lo += Sv[nf][0] + Sv[nf][1];
            ps_hi += Sv[nf][2] + Sv[nf][3];
        }
        ps_lo += __shfl_xor_sync(0xffffffffu, ps_lo, 1);
        ps_lo += __shfl_xor_sync(0xffffffffu, ps_lo, 2);
        ps_hi += __shfl_xor_sync(0xffffffffu, ps_hi, 1);
        ps_hi += __shfl_xor_sync(0xffffffffu, ps_hi, 2);
        l_lo = l_lo * corr_lo + ps_lo;
        l_hi = l_hi * corr_hi + ps_hi;

#pragma unroll
        for (int nf = 0; nf < 8; nf++) {
            Oacc[nf][0] *= corr_lo; Oacc[nf][1] *= corr_lo;
            Oacc[nf][2] *= corr_hi; Oacc[nf][3] *= corr_hi;
        }

        // ---- O += P . V (P repacked from registers, 3-split) ----
#pragma unroll
        for (int ks = 0; ks < 4; ks++) {
            uint32_t pa_h[4], pa_l[4];
            pa_h[0] = bfpack(Sv[2 * ks][0], Sv[2 * ks][1]);
            pa_h[1] = bfpack(Sv[2 * ks][2], Sv[2 * ks][3]);
            pa_h[2] = bfpack(Sv[2 * ks + 1][0], Sv[2 * ks + 1][1]);
            pa_h[3] = bfpack(Sv[2 * ks + 1][2], Sv[2 * ks + 1][3]);
            pa_l[0] = bfpack(Sv[2 * ks][0] - __uint_as_float(pa_h[0] << 16),
                             Sv[2 * ks][1] - __uint_as_float(pa_h[0] & 0xffff0000u));
            pa_l[1] = bfpack(Sv[2 * ks][2] - __uint_as_float(pa_h[1] << 16),
                             Sv[2 * ks][3] - __uint_as_float(pa_h[1] & 0xffff0000u));
            pa_l[2] = bfpack(Sv[2 * ks + 1][0] - __uint_as_float(pa_h[2] << 16),
                             Sv[2 * ks + 1][1] - __uint_as_float(pa_h[2] & 0xffff0000u));
            pa_l[3] = bfpack(Sv[2 * ks + 1][2] - __uint_as_float(pa_h[3] << 16),
                             Sv[2 * ks + 1][3] - __uint_as_float(pa_h[3] & 0xffff0000u));
#pragma unroll
            for (int nf2 = 0; nf2 < 4; nf2++) {
                uint32_t vh4[4], vl4[4];
                uint32_t ad = st + 2 * PL
                            + (ks * 16 + (lane & 7) + ((lane >> 3) & 1) * 8) * PITCH
                            + (nf2 * 16 + (lane >> 4) * 8) * 2;
                ldm_x4t(vh4, ad);
                ldm_x4t(vl4, ad + PL);
                mma_b(Oacc[2 * nf2],     pa_h, vh4[0], vh4[1]);
                mma_b(Oacc[2 * nf2],     pa_h, vl4[0], vl4[1]);
                mma_b(Oacc[2 * nf2],     pa_l, vh4[0], vh4[1]);
                mma_b(Oacc[2 * nf2 + 1], pa_h, vh4[2], vh4[3]);
                mma_b(Oacc[2 * nf2 + 1], pa_h, vl4[2], vl4[3]);
                mma_b(Oacc[2 * nf2 + 1], pa_l, vh4[2], vh4[3]);
            }
        }
        __syncthreads();   // all reads of stage buf done before it is rewritten
    }

    // ---- epilogue: O / l -> split planes for the Wo GEMM ----
    float inv_lo = 1.0f / l_lo, inv_hi = 1.0f / l_hi;
    size_t ob = ((size_t)b * SEQ + q0 + rt) * DMODEL + h * DKV;
#pragma unroll
    for (int nf = 0; nf < 8; nf++) {
        int c = nf * 8 + cq;
#pragma unroll
        for (int half = 0; half < 2; half++) {
            float v0 = Oacc[nf][half * 2] * (half ? inv_hi : inv_lo);
            float v1 = Oacc[nf][half * 2 + 1] * (half ? inv_hi : inv_lo);
            uint32_t uh = bfpack(v0, v1);
            float e0 = v0 - __uint_as_float(uh << 16);
            float e1 = v1 - __uint_as_float(uh & 0xffff0000u);
            uint32_t ul = bfpack(e0, e1);
            size_t idx = ob + half * (size_t)(8 * DMODEL) + c;
            *(uint32_t*)&g_phi[idx] = uh;
            *(uint32_t*)&g_plo[idx] = ul;
        }
    }
}

// ---------------- launcher ---------------------------------------------------
extern "C" void kernel_launch(void* const* d_in, const int* in_sizes, int n_in,
                              void* d_out, int out_size) {
    const float* hidden = (const float*)d_in[0];
    const float* Wq     = (const float*)d_in[1];
    const float* Wk     = (const float*)d_in[2];
    const float* Wv     = (const float*)d_in[3];
    const float* Wo     = (const float*)d_in[4];
    const float* table  = (const float*)d_in[5];
    float* out = (float*)d_out;

    cudaFuncSetAttribute(gemm_bf16, cudaFuncAttributeMaxDynamicSharedMemorySize, GEMM_SMEM);
    cudaFuncSetAttribute(attn_tc, cudaFuncAttributeMaxDynamicSharedMemorySize, ATT_SMEM);

    bias_kernel<<<(HEADS * BIAS_PAD + 255) / 256, 256>>>(table);
    split_hidden<<<MTOT * DMODEL / 4 / 256, 256>>>(hidden);
    split_w<<<dim3(DMODEL * DMODEL / 4 / 256, 1, 4), 256>>>(Wq, Wk, Wv, Wo);

    // fused QKV projection: z = 0/1/2 -> W planes 0/1/2, split q/k/v outputs
    dim3 qkv_grid(DMODEL / 128, MTOT / 128, 3);
    gemm_bf16<<<qkv_grid, 256, GEMM_SMEM>>>(0, 1, 0, nullptr);

    attn_tc<<<dim3(SEQ / 128, HEADS, BATCH), 256, ATT_SMEM>>>();

    // output projection: A = attention planes, W plane 3, fp32 out
    dim3 o_grid(DMODEL / 128, MTOT / 128, 1);
    gemm_bf16<<<o_grid, 256, GEMM_SMEM>>>(1, 0, 3, out);
}

// round 13
// speedup vs baseline: 1.0489x; 1.0489x over previous
#include <cuda_runtime.h>
#include <cstdint>

#define BATCH   2
#define HEADS   16
#define SEQ     2048
#define DKV     64
#define DMODEL  1024
#define MTOT    (BATCH * SEQ)      // 4096 rows
#define BIAS_PAD    4352
#define BIAS_CENTER 2176
#define QKV_ELEMS (BATCH * HEADS * SEQ * DKV)

// ---------------- bf16 pack + tensor-core helpers ---------------------------
__device__ __forceinline__ uint32_t bfpack(float lo_e, float hi_e) {
    uint32_t r; asm("cvt.rn.bf16x2.f32 %0, %1, %2;" : "=r"(r) : "f"(hi_e), "f"(lo_e));
    return r;
}
__device__ __forceinline__ uint32_t smem_u32(const void* p) {
    uint32_t a;
    asm("{ .reg .u64 t; cvta.to.shared.u64 t, %1; cvt.u32.u64 %0, t; }" : "=r"(a) : "l"(p));
    return a;
}
__device__ __forceinline__ void ldm_x4(uint32_t* r, uint32_t addr) {
    asm volatile("ldmatrix.sync.aligned.m8n8.x4.shared.b16 {%0,%1,%2,%3}, [%4];"
        : "=r"(r[0]), "=r"(r[1]), "=r"(r[2]), "=r"(r[3]) : "r"(addr));
}
__device__ __forceinline__ void ldm_x4t(uint32_t* r, uint32_t addr) {
    asm volatile("ldmatrix.sync.aligned.m8n8.x4.trans.shared.b16 {%0,%1,%2,%3}, [%4];"
        : "=r"(r[0]), "=r"(r[1]), "=r"(r[2]), "=r"(r[3]) : "r"(addr));
}
__device__ __forceinline__ void mma_b(float* c, const uint32_t* a, uint32_t b0, uint32_t b1) {
    asm volatile("mma.sync.aligned.m16n8k16.row.col.f32.bf16.bf16.f32 "
        "{%0,%1,%2,%3}, {%4,%5,%6,%7}, {%8,%9}, {%0,%1,%2,%3};"
        : "+f"(c[0]), "+f"(c[1]), "+f"(c[2]), "+f"(c[3])
        : "r"(a[0]), "r"(a[1]), "r"(a[2]), "r"(a[3]), "r"(b0), "r"(b1));
}
// cp.async: 16-byte gmem -> smem, bypassing registers
__device__ __forceinline__ void cp16(uint32_t dst, const void* src) {
    asm volatile("cp.async.cg.shared.global [%0], [%1], 16;" :: "r"(dst), "l"(src));
}
#define CP_COMMIT()  asm volatile("cp.async.commit_group;" ::: "memory")
#define CP_WAIT(n)   asm volatile("cp.async.wait_group %0;" :: "n"(n) : "memory")

// split a float4 into packed-bf16 hi pair + residual-lo pair
__device__ __forceinline__ void split4(float4 v, uint2& hi, uint2& lo) {
    uint32_t h01 = bfpack(v.x, v.y), h23 = bfpack(v.z, v.w);
    float l0 = v.x - __uint_as_float(h01 << 16);
    float l1 = v.y - __uint_as_float(h01 & 0xffff0000u);
    float l2 = v.z - __uint_as_float(h23 << 16);
    float l3 = v.w - __uint_as_float(h23 & 0xffff0000u);
    hi = make_uint2(h01, h23);
    lo = make_uint2(bfpack(l0, l1), bfpack(l2, l3));
}

// ---------------- scratch (device globals: allocation-guard safe) -----------
__device__ __align__(16) uint16_t g_ahi[MTOT * DMODEL],  g_alo[MTOT * DMODEL];
__device__ __align__(16) uint16_t g_whi[4 * DMODEL * DMODEL], g_wlo[4 * DMODEL * DMODEL];
__device__ __align__(16) uint16_t g_qhi[QKV_ELEMS], g_qlo[QKV_ELEMS];
__device__ __align__(16) uint16_t g_khi[QKV_ELEMS], g_klo[QKV_ELEMS];
__device__ __align__(16) uint16_t g_vhi[QKV_ELEMS], g_vlo[QKV_ELEMS];
__device__ __align__(16) uint16_t g_phi[MTOT * DMODEL], g_plo[MTOT * DMODEL];
__device__ float g_bias[HEADS * BIAS_PAD];

// ---------------- T5 relative-position bias ---------------------------------
__global__ void bias_kernel(const float* __restrict__ table) {
    int i = blockIdx.x * blockDim.x + threadIdx.x;
    if (i >= HEADS * BIAS_PAD) return;
    int h = i / BIAS_PAD;
    int delta = (i % BIAS_PAD) - BIAS_CENTER;
    float v = 0.0f;
    int rp = delta < 0 ? -delta : delta;
    if (rp <= SEQ - 1) {
        int base = (delta > 0) ? 16 : 0;
        int bucket;
        if (rp < 8) {
            bucket = base + rp;
        } else {
            float ratio = logf((float)rp * 0.125f) / (float)2.772588722239781;
            int rpl = 8 + (int)(ratio * 8.0f);
            bucket = base + (rpl < 15 ? rpl : 15);
        }
        v = table[bucket * HEADS + h];
    }
    g_bias[i] = v;
}

// ---------------- one-time split passes --------------------------------------
__global__ void split_hidden(const float* __restrict__ x) {
    int i = blockIdx.x * blockDim.x + threadIdx.x;
    if (i >= MTOT * DMODEL / 4) return;
    uint2 hi, lo;
    split4(((const float4*)x)[i], hi, lo);
    ((uint2*)g_ahi)[i] = hi;
    ((uint2*)g_alo)[i] = lo;
}
__global__ void split_w(const float* __restrict__ Wq, const float* __restrict__ Wk,
                        const float* __restrict__ Wv, const float* __restrict__ Wo) {
    int z = blockIdx.z;
    const float* W = (z == 0) ? Wq : (z == 1) ? Wk : (z == 2) ? Wv : Wo;
    int i = blockIdx.x * blockDim.x + threadIdx.x;
    if (i >= DMODEL * DMODEL / 4) return;
    uint2 hi, lo;
    split4(((const float4*)W)[i], hi, lo);
    size_t o = (size_t)z * (DMODEL * DMODEL / 4) + i;
    ((uint2*)g_whi)[o] = hi;
    ((uint2*)g_wlo)[o] = lo;
}

// ---------------- bf16-split tensor-core GEMM, cp.async, term-major MMAs ----
#define APITCH 80
#define BPITCH 272
#define ST_ALO 10240
#define ST_BHI 20480
#define ST_BLO 29184
#define STAGE_BYTES 37888
#define GEMM_SMEM (2 * STAGE_BYTES)

__global__ __launch_bounds__(256) void gemm_bf16(int a_sel, int qkv_mode, int wbase,
                                                 float* __restrict__ outp) {
    extern __shared__ __align__(16) char sm[];

    const uint16_t* Ah = a_sel ? g_phi : g_ahi;
    const uint16_t* Al = a_sel ? g_plo : g_alo;

    int tid = threadIdx.x, lane = tid & 31, wid = tid >> 5;
    int wm = wid >> 2, wn = wid & 3;
    int n0 = blockIdx.x * 128, m0 = blockIdx.y * 128;
    int z = blockIdx.z;
    const uint16_t* Wh = g_whi + (size_t)(wbase + z) * DMODEL * DMODEL;
    const uint16_t* Wl = g_wlo + (size_t)(wbase + z) * DMODEL * DMODEL;

    uint32_t sb = smem_u32(sm);

    int a_row[2], a_seg[2], b_row[2], b_seg[2];
#pragma unroll
    for (int r = 0; r < 2; r++) {
        int idx = tid + r * 256;
        a_row[r] = idx >> 2;  a_seg[r] = idx & 3;
        b_row[r] = idx >> 4;  b_seg[r] = idx & 15;
    }

    float acc[4][4][4];
#pragma unroll
    for (int a = 0; a < 4; a++)
#pragma unroll
        for (int b = 0; b < 4; b++)
#pragma unroll
            for (int c = 0; c < 4; c++) acc[a][b][c] = 0.0f;

    uint32_t aoff = (uint32_t)((wm * 64 + (lane & 15)) * APITCH + (lane >> 4) * 16);
    uint32_t boff = (uint32_t)(((lane & 7) + ((lane >> 3) & 1) * 8) * BPITCH
                               + (wn * 32 + (lane >> 4) * 8) * 2);

    auto issue = [&](int ch, int buf) {
        int k0 = ch * 32;
        uint32_t st = sb + buf * STAGE_BYTES;
#pragma unroll
        for (int r = 0; r < 2; r++) {
            uint32_t d = st + a_row[r] * APITCH + a_seg[r] * 16;
            size_t go = (size_t)(m0 + a_row[r]) * DMODEL + k0 + a_seg[r] * 8;
            cp16(d, Ah + go);
            cp16(d + ST_ALO, Al + go);
            uint32_t db = st + ST_BHI + b_row[r] * BPITCH + b_seg[r] * 16;
            size_t gb = (size_t)(k0 + b_row[r]) * DMODEL + n0 + b_seg[r] * 8;
            cp16(db, Wh + gb);
            cp16(db + (ST_BLO - ST_BHI), Wl + gb);
        }
        CP_COMMIT();
    };

    issue(0, 0);
    for (int ch = 0; ch < 32; ch++) {
        int buf = ch & 1;
        if (ch < 31) issue(ch + 1, buf ^ 1);
        if (ch < 31) { CP_WAIT(1); } else { CP_WAIT(0); }
        __syncthreads();

        uint32_t st = sb + buf * STAGE_BYTES;
#pragma unroll
        for (int ks = 0; ks < 2; ks++) {
            uint32_t ahf[4][4], alf[4][4], bhf[2][4], blf[2][4];
#pragma unroll
            for (int mf = 0; mf < 4; mf++) {
                uint32_t ad = st + aoff + mf * (16 * APITCH) + ks * 32;
                ldm_x4(ahf[mf], ad);
                ldm_x4(alf[mf], ad + ST_ALO);
            }
#pragma unroll
            for (int nf2 = 0; nf2 < 2; nf2++) {
                uint32_t bd = st + ST_BHI + boff + nf2 * 32 + ks * (16 * BPITCH);
                ldm_x4t(bhf[nf2], bd);
                ldm_x4t(blf[nf2], bd + (ST_BLO - ST_BHI));
            }
            // term-major issue: 16 independent MMAs between same-acc reuse
#pragma unroll
            for (int mf = 0; mf < 4; mf++)
#pragma unroll
                for (int nf = 0; nf < 4; nf++)
                    mma_b(acc[mf][nf], ahf[mf],
                          bhf[nf >> 1][(nf & 1) * 2], bhf[nf >> 1][(nf & 1) * 2 + 1]);
#pragma unroll
            for (int mf = 0; mf < 4; mf++)
#pragma unroll
                for (int nf = 0; nf < 4; nf++)
                    mma_b(acc[mf][nf], ahf[mf],
                          blf[nf >> 1][(nf & 1) * 2], blf[nf >> 1][(nf & 1) * 2 + 1]);
#pragma unroll
            for (int mf = 0; mf < 4; mf++)
#pragma unroll
                for (int nf = 0; nf < 4; nf++)
                    mma_b(acc[mf][nf], alf[mf],
                          bhf[nf >> 1][(nf & 1) * 2], bhf[nf >> 1][(nf & 1) * 2 + 1]);
        }
        __syncthreads();
    }

    // ---- epilogue ----
    int g = lane >> 2, tg = lane & 3;
    uint16_t* dh = (z == 0) ? g_qhi : (z == 1) ? g_khi : g_vhi;
    uint16_t* dl = (z == 0) ? g_qlo : (z == 1) ? g_klo : g_vlo;
#pragma unroll
    for (int mf = 0; mf < 4; mf++) {
        int r0 = m0 + wm * 64 + mf * 16 + g;
#pragma unroll
        for (int nf = 0; nf < 4; nf++) {
            int c = n0 + wn * 32 + nf * 8 + tg * 2;
            if (qkv_mode) {
                int h = c >> 6, d = c & 63;
#pragma unroll
                for (int half = 0; half < 2; half++) {
                    int r = r0 + half * 8;
                    int b = r >> 11, s = r & (SEQ - 1);
                    float v0 = acc[mf][nf][half * 2], v1 = acc[mf][nf][half * 2 + 1];
                    uint32_t uh = bfpack(v0, v1);
                    float e0 = v0 - __uint_as_float(uh << 16);
                    float e1 = v1 - __uint_as_float(uh & 0xffff0000u);
                    uint32_t ul = bfpack(e0, e1);
                    size_t idx = ((((size_t)(b * HEADS + h)) * SEQ + s) << 6) + d;
                    *(uint32_t*)&dh[idx] = uh;
                    *(uint32_t*)&dl[idx] = ul;
                }
            } else {
                *(float2*)&outp[(size_t)r0 * DMODEL + c] =
                    make_float2(acc[mf][nf][0], acc[mf][nf][1]);
                *(float2*)&outp[(size_t)(r0 + 8) * DMODEL + c] =
                    make_float2(acc[mf][nf][2], acc[mf][nf][3]);
            }
        }
    }
}

// ---------------- tensor-core flash attention (round-11 staging, reordered) --
#define KTILE 64
#define PITCH 144
#define AT_QLO 18432
#define AT_KLO 9216
#define AT_VHI 18432
#define AT_VLO 27648

__global__ __launch_bounds__(256) void attn_tc() {
    __shared__ __align__(16) char smA[36864];
    __shared__ float bias_s[192];

    int tid = threadIdx.x, lane = tid & 31, w = tid >> 5;
    int h = blockIdx.y, b = blockIdx.z;
    int bh = b * HEADS + h;
    int q0 = blockIdx.x * 128;

    uint32_t sb = smem_u32(smA);

    // ---- stage Q tile (pre-split planes, pure copy) ----
    {
        int qrow = tid >> 1, qc0 = (tid & 1) * 32;
        const uint16_t* qpH = g_qhi + ((size_t)bh * SEQ + q0 + qrow) * 64 + qc0;
        const uint16_t* qpL = g_qlo + ((size_t)bh * SEQ + q0 + qrow) * 64 + qc0;
        char* p = smA + qrow * PITCH + qc0 * 2;
#pragma unroll
        for (int i = 0; i < 4; i++) {
            *(uint4*)(p + i * 16) = *(const uint4*)(qpH + i * 8);
            *(uint4*)(p + AT_QLO + i * 16) = *(const uint4*)(qpL + i * 8);
        }
    }
    __syncthreads();

    // ---- Q fragments to registers ----
    uint32_t qh[4][4], ql[4][4];
#pragma unroll
    for (int ks = 0; ks < 4; ks++) {
        uint32_t ad = sb + (w * 16 + (lane & 15)) * PITCH + (lane >> 4) * 16 + ks * 32;
        ldm_x4(qh[ks], ad);
        ldm_x4(ql[ks], ad + AT_QLO);
    }

    // ---- prefetch K/V tile 0 ----
    int krow = tid >> 2, kc0 = (tid & 3) * 16;
    uint4 pkh[2], pkl[2], pvh[2], pvl[2];
    {
        size_t o = ((size_t)bh * SEQ + krow) * 64 + kc0;
#pragma unroll
        for (int i = 0; i < 2; i++) {
            pkh[i] = *(const uint4*)(g_khi + o + i * 8);
            pkl[i] = *(const uint4*)(g_klo + o + i * 8);
            pvh[i] = *(const uint4*)(g_vhi + o + i * 8);
            pvl[i] = *(const uint4*)(g_vlo + o + i * 8);
        }
    }
    __syncthreads();   // all warps done reading Q smem before K/V overwrite

    float Oacc[8][4];
#pragma unroll
    for (int nf = 0; nf < 8; nf++)
#pragma unroll
        for (int j = 0; j < 4; j++) Oacc[nf][j] = 0.0f;

    float m_lo = -1e30f, m_hi = -1e30f, l_lo = 0.0f, l_hi = 0.0f;
    int rq = lane >> 2, cq = 2 * (lane & 3);
    int rt = w * 16 + rq;

    for (int kt = 0; kt < SEQ / KTILE; kt++) {
        int kbase = kt * KTILE;

        // ---- store staged K/V (pure copies) ----
        {
            char* p = smA + krow * PITCH + kc0 * 2;
            *(uint4*)p = pkh[0];
            *(uint4*)(p + 16) = pkh[1];
            *(uint4*)(p + AT_KLO) = pkl[0];
            *(uint4*)(p + AT_KLO + 16) = pkl[1];
            char* pv = smA + AT_VHI + krow * PITCH + kc0 * 2;
            *(uint4*)pv = pvh[0];
            *(uint4*)(pv + 16) = pvh[1];
            *(uint4*)(pv + (AT_VLO - AT_VHI)) = pvl[0];
            *(uint4*)(pv + (AT_VLO - AT_VHI) + 16) = pvl[1];
        }
        if (tid < 192)
            bias_s[tid] = g_bias[h * BIAS_PAD + BIAS_CENTER + kbase - q0 + tid - 127];
        __syncthreads();

        // ---- prefetch next tile ----
        if (kt < SEQ / KTILE - 1) {
            size_t o = ((size_t)bh * SEQ + kbase + KTILE + krow) * 64 + kc0;
#pragma unroll
            for (int i = 0; i < 2; i++) {
                pkh[i] = *(const uint4*)(g_khi + o + i * 8);
                pkl[i] = *(const uint4*)(g_klo + o + i * 8);
                pvh[i] = *(const uint4*)(g_vhi + o + i * 8);
                pvl[i] = *(const uint4*)(g_vlo + o + i * 8);
            }
        }

        // ---- S = Q . K^T (3-split, term-major over nf2 pairs) ----
        float Sv[8][4];
#pragma unroll
        for (int nf = 0; nf < 8; nf++)
#pragma unroll
            for (int j = 0; j < 4; j++) Sv[nf][j] = 0.0f;

#pragma unroll
        for (int ks = 0; ks < 4; ks++) {
#pragma unroll
            for (int p = 0; p < 2; p++) {
                uint32_t kh4[2][4], kl4[2][4];
#pragma unroll
                for (int j = 0; j < 2; j++) {
                    int nf2 = 2 * p + j;
                    uint32_t ad = sb + (nf2 * 16 + (lane & 7) + ((lane >> 4) << 3)) * PITCH
                                  + ((lane >> 3) & 1) * 16 + ks * 32;
                    ldm_x4(kh4[j], ad);
                    ldm_x4(kl4[j], ad + AT_KLO);
                }
                // hh
                mma_b(Sv[4 * p + 0], qh[ks], kh4[0][0], kh4[0][1]);
                mma_b(Sv[4 * p + 1], qh[ks], kh4[0][2], kh4[0][3]);
                mma_b(Sv[4 * p + 2], qh[ks], kh4[1][0], kh4[1][1]);
                mma_b(Sv[4 * p + 3], qh[ks], kh4[1][2], kh4[1][3]);
                // hl
                mma_b(Sv[4 * p + 0], qh[ks], kl4[0][0], kl4[0][1]);
                mma_b(Sv[4 * p + 1], qh[ks], kl4[0][2], kl4[0][3]);
                mma_b(Sv[4 * p + 2], qh[ks], kl4[1][0], kl4[1][1]);
                mma_b(Sv[4 * p + 3], qh[ks], kl4[1][2], kl4[1][3]);
                // lh
                mma_b(Sv[4 * p + 0], ql[ks], kh4[0][0], kh4[0][1]);
                mma_b(Sv[4 * p + 1], ql[ks], kh4[0][2], kh4[0][3]);
                mma_b(Sv[4 * p + 2], ql[ks], kh4[1][0], kh4[1][1]);
                mma_b(Sv[4 * p + 3], ql[ks], kh4[1][2], kh4[1][3]);
            }
        }

        // ---- bias + online softmax ----
        const float* bw = bias_s + 127 - rt;
        float mt_lo = -1e30f, mt_hi = -1e30f;
#pragma unroll
        for (int nf = 0; nf < 8; nf++) {
            int c = nf * 8 + cq;
            Sv[nf][0] += bw[c];
            Sv[nf][1] += bw[c + 1];
            Sv[nf][2] += bw[c - 8];
            Sv[nf][3] += bw[c - 7];
            mt_lo = fmaxf(mt_lo, fmaxf(Sv[nf][0], Sv[nf][1]));
            mt_hi = fmaxf(mt_hi, fmaxf(Sv[nf][2], Sv[nf][3]));
        }
        mt_lo = fmaxf(mt_lo, __shfl_xor_sync(0xffffffffu, mt_lo, 1));
        mt_lo = fmaxf(mt_lo, __shfl_xor_sync(0xffffffffu, mt_lo, 2));
        mt_hi = fmaxf(mt_hi, __shfl_xor_sync(0xffffffffu, mt_hi, 1));
        mt_hi = fmaxf(mt_hi, __shfl_xor_sync(0xffffffffu, mt_hi, 2));

        float mn_lo = fmaxf(m_lo, mt_lo), mn_hi = fmaxf(m_hi, mt_hi);
        float corr_lo = __expf(m_lo - mn_lo), corr_hi = __expf(m_hi - mn_hi);
        m_lo = mn_lo; m_hi = mn_hi;

        float ps_lo = 0.0f, ps_hi = 0.0f;
#pragma unroll
        for (int nf = 0; nf < 8; nf++) {
            Sv[nf][0] = __expf(Sv[nf][0] - mn_lo);
            Sv[nf][1] = __expf(Sv[nf][1] - mn_lo);
            Sv[nf][2] = __expf(Sv[nf][2] - mn_hi);
            Sv[nf][3] = __expf(Sv[nf][3] - mn_hi);
            ps_lo += Sv[nf][0] + Sv[nf][1];
            ps_hi += Sv[nf][2] + Sv[nf][3];
        }
        ps_lo += __shfl_xor_sync(0xffffffffu, ps_lo, 1);
        ps_lo += __shfl_xor_sync(0xffffffffu, ps_lo, 2);
        ps_hi += __shfl_xor_sync(0xffffffffu, ps_hi, 1);
        ps_hi += __shfl_xor_sync(0xffffffffu, ps_hi, 2);
        l_lo = l_lo * corr_lo + ps_lo;
        l_hi = l_hi * corr_hi + ps_hi;

#pragma unroll
        for (int nf = 0; nf < 8; nf++) {
            Oacc[nf][0] *= corr_lo; Oacc[nf][1] *= corr_lo;
            Oacc[nf][2] *= corr_hi; Oacc[nf][3] *= corr_hi;
        }

        // ---- O += P . V (term-major over nf2 pairs) ----
#pragma unroll
        for (int ks = 0; ks < 4; ks++) {
            uint32_t pa_h[4], pa_l[4];
            pa_h[0] = bfpack(Sv[2 * ks][0], Sv[2 * ks][1]);
            pa_h[1] = bfpack(Sv[2 * ks][2], Sv[2 * ks][3]);
            pa_h[2] = bfpack(Sv[2 * ks + 1][0], Sv[2 * ks + 1][1]);
            pa_h[3] = bfpack(Sv[2 * ks + 1][2], Sv[2 * ks + 1][3]);
            pa_l[0] = bfpack(Sv[2 * ks][0] - __uint_as_float(pa_h[0] << 16),
                             Sv[2 * ks][1] - __uint_as_float(pa_h[0] & 0xffff0000u));
            pa_l[1] = bfpack(Sv[2 * ks][2] - __uint_as_float(pa_h[1] << 16),
                             Sv[2 * ks][3] - __uint_as_float(pa_h[1] & 0xffff0000u));
            pa_l[2] = bfpack(Sv[2 * ks + 1][0] - __uint_as_float(pa_h[2] << 16),
                             Sv[2 * ks + 1][1] - __uint_as_float(pa_h[2] & 0xffff0000u));
            pa_l[3] = bfpack(Sv[2 * ks + 1][2] - __uint_as_float(pa_h[3] << 16),
                             Sv[2 * ks + 1][3] - __uint_as_float(pa_h[3] & 0xffff0000u));
#pragma unroll
            for (int p = 0; p < 2; p++) {
                uint32_t vh4[2][4], vl4[2][4];
#pragma unroll
                for (int j = 0; j < 2; j++) {
                    int nf2 = 2 * p + j;
                    uint32_t ad = sb + AT_VHI
                                + (ks * 16 + (lane & 7) + ((lane >> 3) & 1) * 8) * PITCH
                                + (nf2 * 16 + (lane >> 4) * 8) * 2;
                    ldm_x4t(vh4[j], ad);
                    ldm_x4t(vl4[j], ad + (AT_VLO - AT_VHI));
                }
                // hh
                mma_b(Oacc[4 * p + 0], pa_h, vh4[0][0], vh4[0][1]);
                mma_b(Oacc[4 * p + 1], pa_h, vh4[0][2], vh4[0][3]);
                mma_b(Oacc[4 * p + 2], pa_h, vh4[1][0], vh4[1][1]);
                mma_b(Oacc[4 * p + 3], pa_h, vh4[1][2], vh4[1][3]);
                // hl
                mma_b(Oacc[4 * p + 0], pa_h, vl4[0][0], vl4[0][1]);
                mma_b(Oacc[4 * p + 1], pa_h, vl4[0][2], vl4[0][3]);
                mma_b(Oacc[4 * p + 2], pa_h, vl4[1][0], vl4[1][1]);
                mma_b(Oacc[4 * p + 3], pa_h, vl4[1][2], vl4[1][3]);
                // lh
                mma_b(Oacc[4 * p + 0], pa_l, vh4[0][0], vh4[0][1]);
                mma_b(Oacc[4 * p + 1], pa_l, vh4[0][2], vh4[0][3]);
                mma_b(Oacc[4 * p + 2], pa_l, vh4[1][0], vh4[1][1]);
                mma_b(Oacc[4 * p + 3], pa_l, vh4[1][2], vh4[1][3]);
            }
        }
        __syncthreads();   // compute done before next tile's smem store
    }

    // ---- epilogue: O / l -> split planes for the Wo GEMM ----
    float inv_lo = 1.0f / l_lo, inv_hi = 1.0f / l_hi;
    size_t ob = ((size_t)b * SEQ + q0 + rt) * DMODEL + h * DKV;
#pragma unroll
    for (int nf = 0; nf < 8; nf++) {
        int c = nf * 8 + cq;
#pragma unroll
        for (int half = 0; half < 2; half++) {
            float v0 = Oacc[nf][half * 2] * (half ? inv_hi : inv_lo);
            float v1 = Oacc[nf][half * 2 + 1] * (half ? inv_hi : inv_lo);
            uint32_t uh = bfpack(v0, v1);
            float e0 = v0 - __uint_as_float(uh << 16);
            float e1 = v1 - __uint_as_float(uh & 0xffff0000u);
            uint32_t ul = bfpack(e0, e1);
            size_t idx = ob + half * (size_t)(8 * DMODEL) + c;
            *(uint32_t*)&g_phi[idx] = uh;
            *(uint32_t*)&g_plo[idx] = ul;
        }
    }
}

// ---------------- launcher ---------------------------------------------------
extern "C" void kernel_launch(void* const* d_in, const int* in_sizes, int n_in,
                              void* d_out, int out_size) {
    const float* hidden = (const float*)d_in[0];
    const float* Wq     = (const float*)d_in[1];
    const float* Wk     = (const float*)d_in[2];
    const float* Wv     = (const float*)d_in[3];
    const float* Wo     = (const float*)d_in[4];
    const float* table  = (const float*)d_in[5];
    float* out = (float*)d_out;

    cudaFuncSetAttribute(gemm_bf16, cudaFuncAttributeMaxDynamicSharedMemorySize, GEMM_SMEM);

    bias_kernel<<<(HEADS * BIAS_PAD + 255) / 256, 256>>>(table);
    split_hidden<<<MTOT * DMODEL / 4 / 256, 256>>>(hidden);
    split_w<<<dim3(DMODEL * DMODEL / 4 / 256, 1, 4), 256>>>(Wq, Wk, Wv, Wo);

    // fused QKV projection: z = 0/1/2 -> W planes 0/1/2, split q/k/v outputs
    dim3 qkv_grid(DMODEL / 128, MTOT / 128, 3);
    gemm_bf16<<<qkv_grid, 256, GEMM_SMEM>>>(0, 1, 0, nullptr);

    attn_tc<<<dim3(SEQ / 128, HEADS, BATCH), 256>>>();

    // output projection: A = attention planes, W plane 3, fp32 out
    dim3 o_grid(DMODEL / 128, MTOT / 128, 1);
    gemm_bf16<<<o_grid, 256, GEMM_SMEM>>>(1, 0, 3, out);
}